// round 16
// baseline (speedup 1.0000x reference)
#include <cuda_runtime.h>
#include <cuda_fp16.h>
#include <mma.h>
#include <cstdint>
#include <math.h>

using namespace nvcuda;

// Problem constants
#define TT   2048
#define CC   4096
#define NH   32
#define NKV  8
#define HD   128
#define KVC  1024
#define HID  11008
#define EPSF 1e-6f
#define ISCALE 0.08838834764831843f   // 1/sqrt(128)

#define CQKV (CC + 2 * KVC)     // 6144
#define C13  (2 * HID)          // 22016

// ---------------- scratch (device globals) ----------------------------------
__device__ float g_x1  [(size_t)TT * CC];
__device__ __half g_xnh [(size_t)TT * CC];
__device__ __half g_qh  [(size_t)TT * CC];
__device__ __half g_kh  [(size_t)TT * KVC];
__device__ __half g_vth [(size_t)NKV * HD * TT];
__device__ __half g_ph  [(size_t)NH * TT * TT];   // f16 scores -> probs (in place)
__device__ __half g_atth[(size_t)TT * CC];
__device__ __half g_h1h [(size_t)TT * HID];
__device__ __half g_wqkvh[(size_t)CQKV * CC];
__device__ __half g_woh  [(size_t)CC * CC];
__device__ __half g_w13i [(size_t)C13 * CC];    // interleaved w1/w3 rows
__device__ __half g_w2h  [(size_t)CC * HID];

__device__ __forceinline__ uint32_t h2_to_u32(__half2 h) {
    uint32_t u;
    memcpy(&u, &h, 4);
    return u;
}

// =================== weight rounding (f32 -> f16, streaming, 32B/thread) ====
__global__ __launch_bounds__(256) void roundh_k(
    const float4* __restrict__ src, uint4* __restrict__ dst, int n8)
{
    int i = blockIdx.x * 256 + threadIdx.x;
    if (i >= n8) return;
    float4 a, b;
    asm volatile("ld.global.cs.v4.f32 {%0,%1,%2,%3}, [%4];"
        : "=f"(a.x), "=f"(a.y), "=f"(a.z), "=f"(a.w) : "l"(src + 2 * i));
    asm volatile("ld.global.cs.v4.f32 {%0,%1,%2,%3}, [%4];"
        : "=f"(b.x), "=f"(b.y), "=f"(b.z), "=f"(b.w) : "l"(src + 2 * i + 1));
    uint4 o;
    o.x = h2_to_u32(__floats2half2_rn(a.x, a.y));
    o.y = h2_to_u32(__floats2half2_rn(a.z, a.w));
    o.z = h2_to_u32(__floats2half2_rn(b.x, b.y));
    o.w = h2_to_u32(__floats2half2_rn(b.z, b.w));
    asm volatile("st.global.cs.v4.u32 [%0], {%1,%2,%3,%4};"
        :: "l"(dst + i), "r"(o.x), "r"(o.y), "r"(o.z), "r"(o.w));
}

// w1/w3 -> interleaved rows: dst row 2j = w1 row j, dst row 2j+1 = w3 row j
__global__ __launch_bounds__(256) void roundh13_k(
    const float4* __restrict__ w1, const float4* __restrict__ w3,
    uint4* __restrict__ dst, int n8)
{
    int i = blockIdx.x * 256 + threadIdx.x;
    if (i >= n8) return;
    int row = i >> 9;           // /512 (CC/8 chunks per row)
    int c   = i & 511;
    #pragma unroll
    for (int s = 0; s < 2; s++) {
        const float4* src = (s == 0) ? w1 : w3;
        float4 a, b;
        asm volatile("ld.global.cs.v4.f32 {%0,%1,%2,%3}, [%4];"
            : "=f"(a.x), "=f"(a.y), "=f"(a.z), "=f"(a.w) : "l"(src + 2 * i));
        asm volatile("ld.global.cs.v4.f32 {%0,%1,%2,%3}, [%4];"
            : "=f"(b.x), "=f"(b.y), "=f"(b.z), "=f"(b.w) : "l"(src + 2 * i + 1));
        uint4 o;
        o.x = h2_to_u32(__floats2half2_rn(a.x, a.y));
        o.y = h2_to_u32(__floats2half2_rn(a.z, a.w));
        o.z = h2_to_u32(__floats2half2_rn(b.x, b.y));
        o.w = h2_to_u32(__floats2half2_rn(b.z, b.w));
        size_t doff = (size_t)(2 * row + s) * 512 + c;
        asm volatile("st.global.cs.v4.u32 [%0], {%1,%2,%3,%4};"
            :: "l"(dst + doff), "r"(o.x), "r"(o.y), "r"(o.z), "r"(o.w));
    }
}

// =================== reduce helpers =========================================
__device__ __forceinline__ float blockReduceSum256(float v) {
    __shared__ float sh[8];
    int lane = threadIdx.x & 31, w = threadIdx.x >> 5;
    #pragma unroll
    for (int o = 16; o; o >>= 1) v += __shfl_xor_sync(0xffffffffu, v, o);
    if (lane == 0) sh[w] = v;
    __syncthreads();
    float r = sh[0];
    #pragma unroll
    for (int i = 1; i < 8; i++) r += sh[i];
    return r;
}
__device__ __forceinline__ float blockReduceMax256(float v) {
    __shared__ float sh[8];
    int lane = threadIdx.x & 31, w = threadIdx.x >> 5;
    #pragma unroll
    for (int o = 16; o; o >>= 1) v = fmaxf(v, __shfl_xor_sync(0xffffffffu, v, o));
    if (lane == 0) sh[w] = v;
    __syncthreads();
    float r = sh[0];
    #pragma unroll
    for (int i = 1; i < 8; i++) r = fmaxf(r, sh[i]);
    return r;
}

// =================== elementwise kernels ====================================
__global__ __launch_bounds__(256) void rmsnorm_k(
    const float* __restrict__ x, const float* __restrict__ w, __half* __restrict__ out)
{
    size_t t = blockIdx.x;
    const float* xr = x + t * CC;
    float ss = 0.f;
    for (int i = threadIdx.x; i < CC; i += 256) { float v = xr[i]; ss += v * v; }
    float tot = blockReduceSum256(ss);
    float inv = rsqrtf(tot * (1.0f / CC) + EPSF);
    for (int i = threadIdx.x; i < CC; i += 256)
        out[t * CC + i] = __float2half(xr[i] * inv * w[i]);
}

// in-place f16 softmax with exact causal mask; written region Lpad = 128-aligned
__global__ __launch_bounds__(256) void softmax_k(__half* __restrict__ P)
{
    size_t row = blockIdx.x;
    int t = (int)(row & (TT - 1));
    int Lpad = ((t >> 7) << 7) + 128;
    __half* r = P + row * TT;
    int tid = threadIdx.x;
    float v[8];
    float mx = -1e30f;
    #pragma unroll
    for (int j = 0; j < 8; j++) {
        int idx = tid + j * 256;
        v[j] = (idx <= t) ? __half2float(r[idx]) : -1e30f;
        mx = fmaxf(mx, v[j]);
    }
    mx = blockReduceMax256(mx);
    float sum = 0.f;
    #pragma unroll
    for (int j = 0; j < 8; j++) { v[j] = __expf(v[j] - mx); sum += v[j]; }
    sum = blockReduceSum256(sum);
    float inv = 1.0f / sum;
    #pragma unroll
    for (int j = 0; j < 8; j++) {
        int idx = tid + j * 256;
        if (idx < Lpad) r[idx] = (idx <= t) ? __float2half(v[j] * inv) : __half(0);
    }
}

// =================== fp16 WMMA GEMM (128x128 CTA, 3-stage, 1 sync/tile) =====
#define BM 128
#define BN 128
#define BK 64
#define LDSH 72
#define NSTAGE 3
#define STAGE_HALVES (2 * BM * LDSH)
#define SMEM_BYTES (NSTAGE * STAGE_HALVES * 2)   // 110,592

__device__ __forceinline__ uint32_t smem_u32(const void* p) {
    uint32_t a;
    asm("{ .reg .u64 t; cvta.to.shared.u64 t, %1; cvt.u32.u64 %0, t; }" : "=r"(a) : "l"(p));
    return a;
}
__device__ __forceinline__ void cp16(uint32_t dst, const void* src) {
    asm volatile("cp.async.cg.shared.global [%0], [%1], 16;" :: "r"(dst), "l"(src));
}
#define CP_COMMIT()  asm volatile("cp.async.commit_group;" ::: "memory")
#define CP_WAIT(n)   asm volatile("cp.async.wait_group %0;" :: "n"(n) : "memory")

// C[M,N](+z*sC) = init + A[M,K](+z*sA) * B[N,K]^T(+(z/bdiv)*sB)  (A,B f16)
// EPI: 0 f32 acc=0 | 1 f32 acc=I residual | 2 f16 store + masked-tile skip
//      3 f16 store acc=0 | 4 f16 silu-gate store | 5 qkv rope/transpose store
template<int EPI>
__global__ __launch_bounds__(256, 2) void wgemm(
    int M, int N, int K, int kcausal,
    const __half* __restrict__ A, int lda, size_t sA,
    const __half* __restrict__ B, int ldb, size_t sB, int bdiv,
    void* __restrict__ Cv, int ldc, size_t sC,
    const float* __restrict__ I,
    const float* __restrict__ FC, const float* __restrict__ FS)
{
    extern __shared__ char smc[];
    __half* smh = (__half*)smc;
    int tid = threadIdx.x;
    int m0 = blockIdx.y * BM;
    int n0 = blockIdx.x * BN;
    int z  = blockIdx.z;
    A += (size_t)z * sA;
    B += (size_t)(z / bdiv) * sB;

    if (EPI == 2 && n0 > m0 + BM - 1) return;   // fully-masked tile

    int KT = K / BK;
    if (kcausal) { int lim = (m0 + BM) / BK; if (lim < KT) KT = lim; }

    int wid = tid >> 5;
    int wm = wid & 1;
    int wn = wid >> 1;
    int wrow = m0 + wm * 64;
    int wcol = n0 + wn * 32;

    wmma::fragment<wmma::accumulator, 16, 16, 16, float> acc[4][2];
    #pragma unroll
    for (int mi = 0; mi < 4; mi++)
        #pragma unroll
        for (int ni = 0; ni < 2; ni++) {
            if (EPI == 1) wmma::load_matrix_sync(acc[mi][ni],
                     I + (size_t)(wrow + mi * 16) * ldc + wcol + ni * 16,
                     ldc, wmma::mem_row_major);
            else wmma::fill_fragment(acc[mi][ni], 0.0f);
        }

    int c  = tid & 7;
    int r0 = tid >> 3;
    uint32_t sbase = smem_u32(smh);
    const __half* Ap = A + (size_t)(m0 + r0) * lda + c * 8;
    const __half* Bp = B + (size_t)(n0 + r0) * ldb + c * 8;

    auto issue_stage = [&](int buf, int t) {
        uint32_t as = sbase + (uint32_t)(buf * STAGE_HALVES) * 2u;
        uint32_t bs = as + (uint32_t)(BM * LDSH) * 2u;
        int ko = t * BK;
        #pragma unroll
        for (int i = 0; i < 4; i++) {
            uint32_t soff = (uint32_t)((r0 + 32 * i) * LDSH + c * 8) * 2u;
            cp16(as + soff, Ap + (size_t)(32 * i) * lda + ko);
            cp16(bs + soff, Bp + (size_t)(32 * i) * ldb + ko);
        }
        CP_COMMIT();
    };

    issue_stage(0, 0);
    if (KT > 1) issue_stage(1, 1);

    for (int t = 0; t < KT; t++) {
        if (t + 1 < KT) CP_WAIT(1); else CP_WAIT(0);
        __syncthreads();
        if (t + 2 < KT) issue_stage((t + 2) % NSTAGE, t + 2);

        const __half* Ab = smh + (t % NSTAGE) * STAGE_HALVES;
        const __half* Bb = Ab + BM * LDSH;
        #pragma unroll
        for (int ks = 0; ks < BK / 16; ks++) {
            wmma::fragment<wmma::matrix_a, 16, 16, 16, __half, wmma::row_major> af[4];
            wmma::fragment<wmma::matrix_b, 16, 16, 16, __half, wmma::col_major> bf[2];
            #pragma unroll
            for (int mi = 0; mi < 4; mi++)
                wmma::load_matrix_sync(af[mi], Ab + (wm * 64 + mi * 16) * LDSH + ks * 16, LDSH);
            #pragma unroll
            for (int ni = 0; ni < 2; ni++)
                wmma::load_matrix_sync(bf[ni], Bb + (wn * 32 + ni * 16) * LDSH + ks * 16, LDSH);
            #pragma unroll
            for (int mi = 0; mi < 4; mi++)
                #pragma unroll
                for (int ni = 0; ni < 2; ni++)
                    wmma::mma_sync(acc[mi][ni], af[mi], bf[ni], acc[mi][ni]);
        }
    }

    if (EPI == 2 || EPI == 3 || EPI == 4 || EPI == 5) {
        __syncthreads();
        float* sepi = (float*)smc;     // 128 x 132 f32 = 67.6KB
        #pragma unroll
        for (int mi = 0; mi < 4; mi++)
            #pragma unroll
            for (int ni = 0; ni < 2; ni++)
                wmma::store_matrix_sync(
                    sepi + (wm * 64 + mi * 16) * 132 + wn * 32 + ni * 16,
                    acc[mi][ni], 132, wmma::mem_row_major);
        __syncthreads();
        if (EPI == 2 || EPI == 3) {
            __half* Ch = (__half*)Cv + (size_t)z * sC;
            #pragma unroll
            for (int e = 0; e < 64; e++) {
                int idx = tid + e * 256;
                int row = idx >> 7, col = idx & 127;
                Ch[(size_t)(m0 + row) * ldc + n0 + col] = __float2half(sepi[row * 132 + col]);
            }
        } else if (EPI == 4) {
            // silu-gate: pairs (2k, 2k+1) -> output col (n0/2 + k)
            __half* Ch = (__half*)Cv + (size_t)z * sC;
            int hbase = n0 >> 1;
            #pragma unroll
            for (int e = 0; e < 32; e++) {
                int idx = tid + e * 256;
                int row = idx >> 6, k = idx & 63;
                float a = sepi[row * 132 + 2 * k];
                float b = sepi[row * 132 + 2 * k + 1];
                float sg = a / (1.0f + __expf(-a));
                Ch[(size_t)(m0 + row) * ldc + hbase + k] = __float2half(sg * b);
            }
        } else {
            // EPI 5: qkv epilogue. Tile = one head (128 cols), rows = timesteps.
            if (n0 < CC) {
                #pragma unroll
                for (int e = 0; e < 32; e++) {
                    int idx = tid + e * 256;
                    int r = idx >> 6, k = idx & 63;
                    int t = m0 + r;
                    float cth = FC[t * 64 + k], sth = FS[t * 64 + k];
                    float re = sepi[r * 132 + 2 * k];
                    float im = sepi[r * 132 + 2 * k + 1];
                    __half2* o = (__half2*)(&g_qh[(size_t)t * CC + n0 + 2 * k]);
                    *o = __floats2half2_rn((re * cth - im * sth) * ISCALE,
                                           (re * sth + im * cth) * ISCALE);
                }
            } else if (n0 < CC + KVC) {
                int cb = n0 - CC;
                #pragma unroll
                for (int e = 0; e < 32; e++) {
                    int idx = tid + e * 256;
                    int r = idx >> 6, k = idx & 63;
                    int t = m0 + r;
                    float cth = FC[t * 64 + k], sth = FS[t * 64 + k];
                    float re = sepi[r * 132 + 2 * k];
                    float im = sepi[r * 132 + 2 * k + 1];
                    __half2* o = (__half2*)(&g_kh[(size_t)t * KVC + cb + 2 * k]);
                    *o = __floats2half2_rn(re * cth - im * sth,
                                           re * sth + im * cth);
                }
            } else {
                int hb = n0 - CC - KVC;
                #pragma unroll
                for (int e = 0; e < 64; e++) {
                    int idx = tid + e * 256;
                    int hd = idx >> 7, t = idx & 127;
                    g_vth[(size_t)(hb + hd) * TT + m0 + t] =
                        __float2half(sepi[t * 132 + hd]);
                }
            }
        }
    } else {
        float* Cf = (float*)Cv + (size_t)z * sC;
        #pragma unroll
        for (int mi = 0; mi < 4; mi++)
            #pragma unroll
            for (int ni = 0; ni < 2; ni++)
                wmma::store_matrix_sync(
                    Cf + (size_t)(wrow + mi * 16) * ldc + wcol + ni * 16,
                    acc[mi][ni], ldc, wmma::mem_row_major);
    }
}

// =================== launch =================================================
extern "C" void kernel_launch(void* const* d_in, const int* in_sizes, int n_in,
                              void* d_out, int out_size)
{
    const float* x    = (const float*)d_in[0];
    const float* fc   = (const float*)d_in[2];
    const float* fs   = (const float*)d_in[3];
    const float* wq   = (const float*)d_in[5];
    const float* wk   = (const float*)d_in[6];
    const float* wv   = (const float*)d_in[7];
    const float* wo   = (const float*)d_in[8];
    const float* w1   = (const float*)d_in[9];
    const float* w2   = (const float*)d_in[10];
    const float* w3   = (const float*)d_in[11];
    const float* ln1  = (const float*)d_in[12];
    const float* ln2  = (const float*)d_in[13];
    float* out = (float*)d_out;

    float *x1;
    __half *xnh, *qh, *kh, *vth, *ph, *atth, *h1h;
    __half *wqkvh, *woh, *w13i, *w2h;
    cudaGetSymbolAddress((void**)&x1,   g_x1);
    cudaGetSymbolAddress((void**)&xnh,  g_xnh);
    cudaGetSymbolAddress((void**)&qh,   g_qh);
    cudaGetSymbolAddress((void**)&kh,   g_kh);
    cudaGetSymbolAddress((void**)&vth,  g_vth);
    cudaGetSymbolAddress((void**)&ph,   g_ph);
    cudaGetSymbolAddress((void**)&atth, g_atth);
    cudaGetSymbolAddress((void**)&h1h,  g_h1h);
    cudaGetSymbolAddress((void**)&wqkvh,g_wqkvh);
    cudaGetSymbolAddress((void**)&woh,  g_woh);
    cudaGetSymbolAddress((void**)&w13i, g_w13i);
    cudaGetSymbolAddress((void**)&w2h,  g_w2h);

    cudaFuncSetAttribute(wgemm<1>, cudaFuncAttributeMaxDynamicSharedMemorySize, SMEM_BYTES);
    cudaFuncSetAttribute(wgemm<2>, cudaFuncAttributeMaxDynamicSharedMemorySize, SMEM_BYTES);
    cudaFuncSetAttribute(wgemm<3>, cudaFuncAttributeMaxDynamicSharedMemorySize, SMEM_BYTES);
    cudaFuncSetAttribute(wgemm<4>, cudaFuncAttributeMaxDynamicSharedMemorySize, SMEM_BYTES);
    cudaFuncSetAttribute(wgemm<5>, cudaFuncAttributeMaxDynamicSharedMemorySize, SMEM_BYTES);

    auto RH = [&](const float* src, __half* dst, size_t n) {
        int n8 = (int)(n / 8);
        roundh_k<<<(n8 + 255) / 256, 256>>>((const float4*)src, (uint4*)dst, n8);
    };
    RH(wq, wqkvh,                           (size_t)CC  * CC);
    RH(wk, wqkvh + (size_t)CC * CC,         (size_t)KVC * CC);
    RH(wv, wqkvh + (size_t)(CC + KVC) * CC, (size_t)KVC * CC);
    RH(wo, woh,                             (size_t)CC  * CC);
    RH(w2, w2h,                             (size_t)CC  * HID);
    {
        int n8 = (int)(((size_t)HID * CC) / 8);
        roundh13_k<<<(n8 + 255) / 256, 256>>>(
            (const float4*)w1, (const float4*)w3, (uint4*)w13i, n8);
    }

    // 1) xn = rmsnorm(x, ln1) -> f16
    rmsnorm_k<<<TT, 256>>>(x, ln1, xnh);

    // 2) fused qkv projection with rope/transpose epilogue -> qh/kh/vth (EPI5)
    wgemm<5><<<dim3(CQKV / BN, TT / BM, 1), 256, SMEM_BYTES>>>(
        TT, CQKV, CC, 0, xnh, CC, 0, wqkvh, CC, 0, 1, nullptr, CQKV, 0,
        nullptr, fc, fs);

    // 3) raw scores = q @ k^T -> f16 in ph (masked 128x128 tiles skipped)
    wgemm<2><<<dim3(TT / BN, TT / BM, NH), 256, SMEM_BYTES>>>(
        TT, TT, HD, 0,
        qh, CC, (size_t)HD,
        kh, KVC, (size_t)HD, 4,
        ph, TT, (size_t)TT * TT,
        nullptr, nullptr, nullptr);

    // 4) in-place f16 softmax with exact causal mask
    softmax_k<<<NH * TT, 256>>>(ph);

    // 5) att = P @ vt^T -> f16 (skip zero K-tiles)
    wgemm<3><<<dim3(HD / BN, TT / BM, NH), 256, SMEM_BYTES>>>(
        TT, HD, TT, 1,
        ph, TT, (size_t)TT * TT,
        vth, TT, (size_t)HD * TT, 4,
        atth, CC, (size_t)HD,
        nullptr, nullptr, nullptr);

    // 6) x1 = x + att @ wo^T (f32)
    wgemm<1><<<dim3(CC / BN, TT / BM, 1), 256, SMEM_BYTES>>>(
        TT, CC, CC, 0, atth, CC, 0, woh, CC, 0, 1, x1, CC, 0, x,
        nullptr, nullptr);

    // 7) xn2 = rmsnorm(x1, ln2) -> f16
    rmsnorm_k<<<TT, 256>>>(x1, ln2, xnh);

    // 8) fused h1 = silu(xn2 @ w1^T) * (xn2 @ w3^T) via interleaved w13 (EPI4)
    wgemm<4><<<dim3(C13 / BN, TT / BM, 1), 256, SMEM_BYTES>>>(
        TT, C13, CC, 0, xnh, CC, 0, w13i, CC, 0, 1, h1h, HID, 0,
        nullptr, nullptr, nullptr);

    // 9) out = x1 + h1 @ w2^T (f32)
    wgemm<1><<<dim3(CC / BN, TT / BM, 1), 256, SMEM_BYTES>>>(
        TT, CC, HID, 0, h1h, HID, 0, w2h, HID, 0, 1, out, CC, 0, x1,
        nullptr, nullptr);
}

// round 17
// speedup vs baseline: 1.0273x; 1.0273x over previous
#include <cuda_runtime.h>
#include <cuda_fp16.h>
#include <mma.h>
#include <cstdint>
#include <math.h>

using namespace nvcuda;

// Problem constants
#define TT   2048
#define CC   4096
#define NH   32
#define NKV  8
#define HD   128
#define KVC  1024
#define HID  11008
#define EPSF 1e-6f
#define ISCALE 0.08838834764831843f   // 1/sqrt(128)

#define CQKV (CC + 2 * KVC)     // 6144
#define C13  (2 * HID)          // 22016

// ---------------- scratch (device globals) ----------------------------------
__device__ float g_s   [(size_t)NH * TT * TT];
__device__ float g_x1  [(size_t)TT * CC];
__device__ __half g_xnh [(size_t)TT * CC];
__device__ __half g_qh  [(size_t)TT * CC];
__device__ __half g_kh  [(size_t)TT * KVC];
__device__ __half g_vth [(size_t)NKV * HD * TT];
__device__ __half g_ph  [(size_t)NH * TT * TT];
__device__ __half g_atth[(size_t)TT * CC];
__device__ __half g_h1h [(size_t)TT * HID];
__device__ __half g_wqkvh[(size_t)CQKV * CC];
__device__ __half g_woh  [(size_t)CC * CC];
__device__ __half g_w13i [(size_t)C13 * CC];    // interleaved w1/w3 rows
__device__ __half g_w2h  [(size_t)CC * HID];

__device__ __forceinline__ uint32_t h2_to_u32(__half2 h) {
    uint32_t u;
    memcpy(&u, &h, 4);
    return u;
}

// =================== merged weight rounding (f32 -> f16, streaming) =========
// Segments in 8-float chunk units:
//   wq [0, 2097152) | wk [.., 2621440) | wv [.., 3145728)
//   wo [.., 5242880) | w2 [.., 10878976)
#define RB0 2097152
#define RB1 2621440
#define RB2 3145728
#define RB3 5242880
#define RTOT 10878976

__global__ __launch_bounds__(256) void roundall_k(
    const float4* __restrict__ wq, const float4* __restrict__ wk,
    const float4* __restrict__ wv, const float4* __restrict__ wo,
    const float4* __restrict__ w2,
    uint4* __restrict__ qkvd, uint4* __restrict__ wod, uint4* __restrict__ w2d)
{
    int i = blockIdx.x * 256 + threadIdx.x;
    if (i >= RTOT) return;
    const float4* s;
    uint4* d;
    if (i < RB0)       { s = wq + 2 * (size_t)i;            d = qkvd + i; }
    else if (i < RB1)  { int j = i - RB0; s = wk + 2 * (size_t)j; d = qkvd + i; }
    else if (i < RB2)  { int j = i - RB1; s = wv + 2 * (size_t)j; d = qkvd + i; }
    else if (i < RB3)  { int j = i - RB2; s = wo + 2 * (size_t)j; d = wod + j; }
    else               { int j = i - RB3; s = w2 + 2 * (size_t)j; d = w2d + j; }
    float4 a, b;
    asm volatile("ld.global.cs.v4.f32 {%0,%1,%2,%3}, [%4];"
        : "=f"(a.x), "=f"(a.y), "=f"(a.z), "=f"(a.w) : "l"(s));
    asm volatile("ld.global.cs.v4.f32 {%0,%1,%2,%3}, [%4];"
        : "=f"(b.x), "=f"(b.y), "=f"(b.z), "=f"(b.w) : "l"(s + 1));
    uint4 o;
    o.x = h2_to_u32(__floats2half2_rn(a.x, a.y));
    o.y = h2_to_u32(__floats2half2_rn(a.z, a.w));
    o.z = h2_to_u32(__floats2half2_rn(b.x, b.y));
    o.w = h2_to_u32(__floats2half2_rn(b.z, b.w));
    asm volatile("st.global.cs.v4.u32 [%0], {%1,%2,%3,%4};"
        :: "l"(d), "r"(o.x), "r"(o.y), "r"(o.z), "r"(o.w));
}

// w1/w3 -> interleaved rows: dst row 2j = w1 row j, dst row 2j+1 = w3 row j
__global__ __launch_bounds__(256) void roundh13_k(
    const float4* __restrict__ w1, const float4* __restrict__ w3,
    uint4* __restrict__ dst, int n8)
{
    int i = blockIdx.x * 256 + threadIdx.x;
    if (i >= n8) return;
    int row = i >> 9;           // /512 (CC/8 chunks per row)
    int c   = i & 511;
    #pragma unroll
    for (int s = 0; s < 2; s++) {
        const float4* src = (s == 0) ? w1 : w3;
        float4 a, b;
        asm volatile("ld.global.cs.v4.f32 {%0,%1,%2,%3}, [%4];"
            : "=f"(a.x), "=f"(a.y), "=f"(a.z), "=f"(a.w) : "l"(src + 2 * i));
        asm volatile("ld.global.cs.v4.f32 {%0,%1,%2,%3}, [%4];"
            : "=f"(b.x), "=f"(b.y), "=f"(b.z), "=f"(b.w) : "l"(src + 2 * i + 1));
        uint4 o;
        o.x = h2_to_u32(__floats2half2_rn(a.x, a.y));
        o.y = h2_to_u32(__floats2half2_rn(a.z, a.w));
        o.z = h2_to_u32(__floats2half2_rn(b.x, b.y));
        o.w = h2_to_u32(__floats2half2_rn(b.z, b.w));
        size_t doff = (size_t)(2 * row + s) * 512 + c;
        asm volatile("st.global.cs.v4.u32 [%0], {%1,%2,%3,%4};"
            :: "l"(dst + doff), "r"(o.x), "r"(o.y), "r"(o.z), "r"(o.w));
    }
}

// =================== reduce helpers =========================================
__device__ __forceinline__ float blockReduceSum256(float v) {
    __shared__ float sh[8];
    int lane = threadIdx.x & 31, w = threadIdx.x >> 5;
    #pragma unroll
    for (int o = 16; o; o >>= 1) v += __shfl_xor_sync(0xffffffffu, v, o);
    if (lane == 0) sh[w] = v;
    __syncthreads();
    float r = sh[0];
    #pragma unroll
    for (int i = 1; i < 8; i++) r += sh[i];
    return r;
}
__device__ __forceinline__ float blockReduceMax256(float v) {
    __shared__ float sh[8];
    int lane = threadIdx.x & 31, w = threadIdx.x >> 5;
    #pragma unroll
    for (int o = 16; o; o >>= 1) v = fmaxf(v, __shfl_xor_sync(0xffffffffu, v, o));
    if (lane == 0) sh[w] = v;
    __syncthreads();
    float r = sh[0];
    #pragma unroll
    for (int i = 1; i < 8; i++) r = fmaxf(r, sh[i]);
    return r;
}

// =================== elementwise kernels ====================================
// vectorized rmsnorm: float4 in, half2 out
__global__ __launch_bounds__(256) void rmsnorm_k(
    const float* __restrict__ x, const float* __restrict__ w, __half* __restrict__ out)
{
    size_t t = blockIdx.x;
    const float4* xr = (const float4*)(x + t * CC);
    const float4* wr = (const float4*)w;
    int tid = threadIdx.x;
    float4 xv[4];
    float ss = 0.f;
    #pragma unroll
    for (int j = 0; j < 4; j++) {
        xv[j] = xr[tid + j * 256];
        ss += xv[j].x * xv[j].x + xv[j].y * xv[j].y
            + xv[j].z * xv[j].z + xv[j].w * xv[j].w;
    }
    float tot = blockReduceSum256(ss);
    float inv = rsqrtf(tot * (1.0f / CC) + EPSF);
    __half2* o2 = (__half2*)(out + t * CC);
    #pragma unroll
    for (int j = 0; j < 4; j++) {
        float4 wv = wr[tid + j * 256];
        int b = (tid + j * 256) * 2;
        o2[b]     = __floats2half2_rn(xv[j].x * inv * wv.x, xv[j].y * inv * wv.y);
        o2[b + 1] = __floats2half2_rn(xv[j].z * inv * wv.z, xv[j].w * inv * wv.w);
    }
}

// vectorized softmax with exact causal mask; f32 scores -> f16 probs
// written region Lpad = 128-aligned
__global__ __launch_bounds__(256) void softmax_k(
    const float* __restrict__ S, __half* __restrict__ P)
{
    size_t row = blockIdx.x;
    int t = (int)(row & (TT - 1));
    int Lpad = ((t >> 7) << 7) + 128;
    const float4* r4 = (const float4*)(S + row * TT);
    __half2* o2 = (__half2*)(P + row * TT);
    int tid = threadIdx.x;
    float v[8];
    float mx = -1e30f;
    #pragma unroll
    for (int h = 0; h < 2; h++) {
        float4 cv = r4[tid + h * 256];
        int base = (tid + h * 256) * 4;
        v[h*4+0] = (base + 0 <= t) ? cv.x : -1e30f;
        v[h*4+1] = (base + 1 <= t) ? cv.y : -1e30f;
        v[h*4+2] = (base + 2 <= t) ? cv.z : -1e30f;
        v[h*4+3] = (base + 3 <= t) ? cv.w : -1e30f;
        #pragma unroll
        for (int e = 0; e < 4; e++) mx = fmaxf(mx, v[h*4+e]);
    }
    mx = blockReduceMax256(mx);
    float sum = 0.f;
    #pragma unroll
    for (int j = 0; j < 8; j++) { v[j] = __expf(v[j] - mx); sum += v[j]; }
    sum = blockReduceSum256(sum);
    float inv = 1.0f / sum;
    #pragma unroll
    for (int h = 0; h < 2; h++) {
        int base = (tid + h * 256) * 4;
        if (base < Lpad) {
            float p0 = (base + 0 <= t) ? v[h*4+0] * inv : 0.f;
            float p1 = (base + 1 <= t) ? v[h*4+1] * inv : 0.f;
            float p2 = (base + 2 <= t) ? v[h*4+2] * inv : 0.f;
            float p3 = (base + 3 <= t) ? v[h*4+3] * inv : 0.f;
            o2[(base >> 1)]     = __floats2half2_rn(p0, p1);
            o2[(base >> 1) + 1] = __floats2half2_rn(p2, p3);
        }
    }
}

// =================== fp16 WMMA GEMM (128x128 CTA, 3-stage, 1 sync/tile) =====
#define BM 128
#define BN 128
#define BK 64
#define LDSH 72
#define NSTAGE 3
#define STAGE_HALVES (2 * BM * LDSH)
#define SMEM_BYTES (NSTAGE * STAGE_HALVES * 2)   // 110,592

__device__ __forceinline__ uint32_t smem_u32(const void* p) {
    uint32_t a;
    asm("{ .reg .u64 t; cvta.to.shared.u64 t, %1; cvt.u32.u64 %0, t; }" : "=r"(a) : "l"(p));
    return a;
}
__device__ __forceinline__ void cp16(uint32_t dst, const void* src) {
    asm volatile("cp.async.cg.shared.global [%0], [%1], 16;" :: "r"(dst), "l"(src));
}
#define CP_COMMIT()  asm volatile("cp.async.commit_group;" ::: "memory")
#define CP_WAIT(n)   asm volatile("cp.async.wait_group %0;" :: "n"(n) : "memory")

// C[M,N](+z*sC) = init + A[M,K](+z*sA) * B[N,K]^T(+(z/bdiv)*sB)  (A,B f16)
// EPI: 0 f32 acc=0 | 1 f32 acc=I residual | 2 f32 acc=0 + masked-tile skip
//      3 f16 store acc=0 | 4 f16 silu-gate store | 5 qkv rope/transpose store
template<int EPI>
__global__ __launch_bounds__(256, 2) void wgemm(
    int M, int N, int K, int kcausal,
    const __half* __restrict__ A, int lda, size_t sA,
    const __half* __restrict__ B, int ldb, size_t sB, int bdiv,
    void* __restrict__ Cv, int ldc, size_t sC,
    const float* __restrict__ I,
    const float* __restrict__ FC, const float* __restrict__ FS)
{
    extern __shared__ char smc[];
    __half* smh = (__half*)smc;
    int tid = threadIdx.x;
    int m0 = blockIdx.y * BM;
    int n0 = blockIdx.x * BN;
    int z  = blockIdx.z;
    A += (size_t)z * sA;
    B += (size_t)(z / bdiv) * sB;

    if (EPI == 2 && n0 > m0 + BM - 1) return;   // fully-masked tile

    int KT = K / BK;
    if (kcausal) { int lim = (m0 + BM) / BK; if (lim < KT) KT = lim; }

    int wid = tid >> 5;
    int wm = wid & 1;
    int wn = wid >> 1;
    int wrow = m0 + wm * 64;
    int wcol = n0 + wn * 32;

    wmma::fragment<wmma::accumulator, 16, 16, 16, float> acc[4][2];
    #pragma unroll
    for (int mi = 0; mi < 4; mi++)
        #pragma unroll
        for (int ni = 0; ni < 2; ni++) {
            if (EPI == 1) wmma::load_matrix_sync(acc[mi][ni],
                     I + (size_t)(wrow + mi * 16) * ldc + wcol + ni * 16,
                     ldc, wmma::mem_row_major);
            else wmma::fill_fragment(acc[mi][ni], 0.0f);
        }

    int c  = tid & 7;
    int r0 = tid >> 3;
    uint32_t sbase = smem_u32(smh);
    const __half* Ap = A + (size_t)(m0 + r0) * lda + c * 8;
    const __half* Bp = B + (size_t)(n0 + r0) * ldb + c * 8;

    auto issue_stage = [&](int buf, int t) {
        uint32_t as = sbase + (uint32_t)(buf * STAGE_HALVES) * 2u;
        uint32_t bs = as + (uint32_t)(BM * LDSH) * 2u;
        int ko = t * BK;
        #pragma unroll
        for (int i = 0; i < 4; i++) {
            uint32_t soff = (uint32_t)((r0 + 32 * i) * LDSH + c * 8) * 2u;
            cp16(as + soff, Ap + (size_t)(32 * i) * lda + ko);
            cp16(bs + soff, Bp + (size_t)(32 * i) * ldb + ko);
        }
        CP_COMMIT();
    };

    issue_stage(0, 0);
    if (KT > 1) issue_stage(1, 1);

    for (int t = 0; t < KT; t++) {
        if (t + 1 < KT) CP_WAIT(1); else CP_WAIT(0);
        __syncthreads();
        if (t + 2 < KT) issue_stage((t + 2) % NSTAGE, t + 2);

        const __half* Ab = smh + (t % NSTAGE) * STAGE_HALVES;
        const __half* Bb = Ab + BM * LDSH;
        #pragma unroll
        for (int ks = 0; ks < BK / 16; ks++) {
            wmma::fragment<wmma::matrix_a, 16, 16, 16, __half, wmma::row_major> af[4];
            wmma::fragment<wmma::matrix_b, 16, 16, 16, __half, wmma::col_major> bf[2];
            #pragma unroll
            for (int mi = 0; mi < 4; mi++)
                wmma::load_matrix_sync(af[mi], Ab + (wm * 64 + mi * 16) * LDSH + ks * 16, LDSH);
            #pragma unroll
            for (int ni = 0; ni < 2; ni++)
                wmma::load_matrix_sync(bf[ni], Bb + (wn * 32 + ni * 16) * LDSH + ks * 16, LDSH);
            #pragma unroll
            for (int mi = 0; mi < 4; mi++)
                #pragma unroll
                for (int ni = 0; ni < 2; ni++)
                    wmma::mma_sync(acc[mi][ni], af[mi], bf[ni], acc[mi][ni]);
        }
    }

    if (EPI == 3 || EPI == 4 || EPI == 5) {
        __syncthreads();
        float* sepi = (float*)smc;     // 128 x 132 f32 = 67.6KB
        #pragma unroll
        for (int mi = 0; mi < 4; mi++)
            #pragma unroll
            for (int ni = 0; ni < 2; ni++)
                wmma::store_matrix_sync(
                    sepi + (wm * 64 + mi * 16) * 132 + wn * 32 + ni * 16,
                    acc[mi][ni], 132, wmma::mem_row_major);
        __syncthreads();
        if (EPI == 3) {
            __half* Ch = (__half*)Cv + (size_t)z * sC;
            #pragma unroll
            for (int e = 0; e < 64; e++) {
                int idx = tid + e * 256;
                int row = idx >> 7, col = idx & 127;
                Ch[(size_t)(m0 + row) * ldc + n0 + col] = __float2half(sepi[row * 132 + col]);
            }
        } else if (EPI == 4) {
            // silu-gate: pairs (2k, 2k+1) -> output col (n0/2 + k)
            __half* Ch = (__half*)Cv + (size_t)z * sC;
            int hbase = n0 >> 1;
            #pragma unroll
            for (int e = 0; e < 32; e++) {
                int idx = tid + e * 256;
                int row = idx >> 6, k = idx & 63;
                float a = sepi[row * 132 + 2 * k];
                float b = sepi[row * 132 + 2 * k + 1];
                float sg = a / (1.0f + __expf(-a));
                Ch[(size_t)(m0 + row) * ldc + hbase + k] = __float2half(sg * b);
            }
        } else {
            // EPI 5: qkv epilogue. Tile = one head (128 cols), rows = timesteps.
            if (n0 < CC) {
                #pragma unroll
                for (int e = 0; e < 32; e++) {
                    int idx = tid + e * 256;
                    int r = idx >> 6, k = idx & 63;
                    int t = m0 + r;
                    float cth = FC[t * 64 + k], sth = FS[t * 64 + k];
                    float re = sepi[r * 132 + 2 * k];
                    float im = sepi[r * 132 + 2 * k + 1];
                    __half2* o = (__half2*)(&g_qh[(size_t)t * CC + n0 + 2 * k]);
                    *o = __floats2half2_rn((re * cth - im * sth) * ISCALE,
                                           (re * sth + im * cth) * ISCALE);
                }
            } else if (n0 < CC + KVC) {
                int cb = n0 - CC;
                #pragma unroll
                for (int e = 0; e < 32; e++) {
                    int idx = tid + e * 256;
                    int r = idx >> 6, k = idx & 63;
                    int t = m0 + r;
                    float cth = FC[t * 64 + k], sth = FS[t * 64 + k];
                    float re = sepi[r * 132 + 2 * k];
                    float im = sepi[r * 132 + 2 * k + 1];
                    __half2* o = (__half2*)(&g_kh[(size_t)t * KVC + cb + 2 * k]);
                    *o = __floats2half2_rn(re * cth - im * sth,
                                           re * sth + im * cth);
                }
            } else {
                int hb = n0 - CC - KVC;
                #pragma unroll
                for (int e = 0; e < 64; e++) {
                    int idx = tid + e * 256;
                    int hd = idx >> 7, t = idx & 127;
                    g_vth[(size_t)(hb + hd) * TT + m0 + t] =
                        __float2half(sepi[t * 132 + hd]);
                }
            }
        }
    } else {
        float* Cf = (float*)Cv + (size_t)z * sC;
        #pragma unroll
        for (int mi = 0; mi < 4; mi++)
            #pragma unroll
            for (int ni = 0; ni < 2; ni++)
                wmma::store_matrix_sync(
                    Cf + (size_t)(wrow + mi * 16) * ldc + wcol + ni * 16,
                    acc[mi][ni], ldc, wmma::mem_row_major);
    }
}

// =================== launch =================================================
extern "C" void kernel_launch(void* const* d_in, const int* in_sizes, int n_in,
                              void* d_out, int out_size)
{
    const float* x    = (const float*)d_in[0];
    const float* fc   = (const float*)d_in[2];
    const float* fs   = (const float*)d_in[3];
    const float* wq   = (const float*)d_in[5];
    const float* wk   = (const float*)d_in[6];
    const float* wv   = (const float*)d_in[7];
    const float* wo   = (const float*)d_in[8];
    const float* w1   = (const float*)d_in[9];
    const float* w2   = (const float*)d_in[10];
    const float* w3   = (const float*)d_in[11];
    const float* ln1  = (const float*)d_in[12];
    const float* ln2  = (const float*)d_in[13];
    float* out = (float*)d_out;

    float *s, *x1;
    __half *xnh, *qh, *kh, *vth, *ph, *atth, *h1h;
    __half *wqkvh, *woh, *w13i, *w2h;
    cudaGetSymbolAddress((void**)&s,    g_s);
    cudaGetSymbolAddress((void**)&x1,   g_x1);
    cudaGetSymbolAddress((void**)&xnh,  g_xnh);
    cudaGetSymbolAddress((void**)&qh,   g_qh);
    cudaGetSymbolAddress((void**)&kh,   g_kh);
    cudaGetSymbolAddress((void**)&vth,  g_vth);
    cudaGetSymbolAddress((void**)&ph,   g_ph);
    cudaGetSymbolAddress((void**)&atth, g_atth);
    cudaGetSymbolAddress((void**)&h1h,  g_h1h);
    cudaGetSymbolAddress((void**)&wqkvh,g_wqkvh);
    cudaGetSymbolAddress((void**)&woh,  g_woh);
    cudaGetSymbolAddress((void**)&w13i, g_w13i);
    cudaGetSymbolAddress((void**)&w2h,  g_w2h);

    cudaFuncSetAttribute(wgemm<1>, cudaFuncAttributeMaxDynamicSharedMemorySize, SMEM_BYTES);
    cudaFuncSetAttribute(wgemm<2>, cudaFuncAttributeMaxDynamicSharedMemorySize, SMEM_BYTES);
    cudaFuncSetAttribute(wgemm<3>, cudaFuncAttributeMaxDynamicSharedMemorySize, SMEM_BYTES);
    cudaFuncSetAttribute(wgemm<4>, cudaFuncAttributeMaxDynamicSharedMemorySize, SMEM_BYTES);
    cudaFuncSetAttribute(wgemm<5>, cudaFuncAttributeMaxDynamicSharedMemorySize, SMEM_BYTES);

    // 0) weight rounding: one merged kernel + interleaved w13
    roundall_k<<<(RTOT + 255) / 256, 256>>>(
        (const float4*)wq, (const float4*)wk, (const float4*)wv,
        (const float4*)wo, (const float4*)w2,
        (uint4*)wqkvh, (uint4*)woh, (uint4*)w2h);
    {
        int n8 = (int)(((size_t)HID * CC) / 8);
        roundh13_k<<<(n8 + 255) / 256, 256>>>(
            (const float4*)w1, (const float4*)w3, (uint4*)w13i, n8);
    }

    // 1) xn = rmsnorm(x, ln1) -> f16
    rmsnorm_k<<<TT, 256>>>(x, ln1, xnh);

    // 2) fused qkv projection with rope/transpose epilogue -> qh/kh/vth (EPI5)
    wgemm<5><<<dim3(CQKV / BN, TT / BM, 1), 256, SMEM_BYTES>>>(
        TT, CQKV, CC, 0, xnh, CC, 0, wqkvh, CC, 0, 1, nullptr, CQKV, 0,
        nullptr, fc, fs);

    // 3) raw scores = q @ k^T (f32; masked 128x128 tiles skipped)
    wgemm<2><<<dim3(TT / BN, TT / BM, NH), 256, SMEM_BYTES>>>(
        TT, TT, HD, 0,
        qh, CC, (size_t)HD,
        kh, KVC, (size_t)HD, 4,
        s, TT, (size_t)TT * TT,
        nullptr, nullptr, nullptr);

    // 4) vectorized softmax with exact causal mask -> f16 probs
    softmax_k<<<NH * TT, 256>>>(s, ph);

    // 5) att = P @ vt^T -> f16 (skip zero K-tiles)
    wgemm<3><<<dim3(HD / BN, TT / BM, NH), 256, SMEM_BYTES>>>(
        TT, HD, TT, 1,
        ph, TT, (size_t)TT * TT,
        vth, TT, (size_t)HD * TT, 4,
        atth, CC, (size_t)HD,
        nullptr, nullptr, nullptr);

    // 6) x1 = x + att @ wo^T (f32)
    wgemm<1><<<dim3(CC / BN, TT / BM, 1), 256, SMEM_BYTES>>>(
        TT, CC, CC, 0, atth, CC, 0, woh, CC, 0, 1, x1, CC, 0, x,
        nullptr, nullptr);

    // 7) xn2 = rmsnorm(x1, ln2) -> f16
    rmsnorm_k<<<TT, 256>>>(x1, ln2, xnh);

    // 8) fused h1 = silu(xn2 @ w1^T) * (xn2 @ w3^T) via interleaved w13 (EPI4)
    wgemm<4><<<dim3(C13 / BN, TT / BM, 1), 256, SMEM_BYTES>>>(
        TT, C13, CC, 0, xnh, CC, 0, w13i, CC, 0, 1, h1h, HID, 0,
        nullptr, nullptr, nullptr);

    // 9) out = x1 + h1 @ w2^T (f32)
    wgemm<1><<<dim3(CC / BN, TT / BM, 1), 256, SMEM_BYTES>>>(
        TT, CC, HID, 0, h1h, HID, 0, w2h, HID, 0, 1, out, CC, 0, x1,
        nullptr, nullptr);
}